// round 2
// baseline (speedup 1.0000x reference)
#include <cuda_runtime.h>

// Problem constants (fixed by the reference):
//   B=16, C=4, H=1024, W=1024
//   x:  [B, C, H, W] fp32
//   wq/wk/wv: [4,4], bq/bk/bv: [4]
//   out: [B, H, C, W] fp32   (after transpose(0,2,1,3))
//
// One CTA per (b,h). 256 threads, each owning 4 consecutive w positions.
// Fully fused: QKV projection -> score reduction over W -> softmax -> attn@V.
// Compulsory traffic only: 16KB in + 16KB out per CTA.

#define H_DIM 1024
#define W_DIM 1024
#define THREADS 256

__global__ __launch_bounds__(THREADS, 8)
void fused_attn_kernel(const float* __restrict__ x,
                       const float* __restrict__ wq, const float* __restrict__ bq,
                       const float* __restrict__ wk, const float* __restrict__ bk,
                       const float* __restrict__ wv, const float* __restrict__ bv,
                       float* __restrict__ out)
{
    const int bh   = blockIdx.x;            // b*H + h
    const int tid  = threadIdx.x;           // 0..255
    const int lane = tid & 31;
    const int warp = tid >> 5;
    const int w0   = tid << 2;              // 4 w per thread

    __shared__ float s_w[48];               // wq | wk | wv  (16 each)
    __shared__ float s_b[12];               // bq | bk | bv  (4 each)
    __shared__ float s_red[8][16];          // per-warp partial scores
    __shared__ float s_scores[16];          // final 4x4 scores (pre-softmax, scaled)

    if (tid < 16) {
        s_w[tid]      = wq[tid];
        s_w[16 + tid] = wk[tid];
        s_w[32 + tid] = wv[tid];
    }
    if (tid < 4) {
        s_b[tid]     = bq[tid];
        s_b[4 + tid] = bk[tid];
        s_b[8 + tid] = bv[tid];
    }
    __syncthreads();

    // ---- Load x: 4 channels x float4 (coalesced: each channel row is 4KB contiguous)
    const int b = bh >> 10;                 // H = 1024
    const int h = bh & (H_DIM - 1);
    const int base = ((b << 2) * H_DIM + h) * W_DIM;   // (b*4 + 0)*H*W + h*W, fits in int (max < 2^27)

    float xv[4][4];
    #pragma unroll
    for (int c = 0; c < 4; c++) {
        float4 t = *reinterpret_cast<const float4*>(x + base + c * (H_DIM * W_DIM) + w0);
        xv[c][0] = t.x; xv[c][1] = t.y; xv[c][2] = t.z; xv[c][3] = t.w;
    }

    // ---- QKV projection per pixel: q[o][j] = bq[o] + sum_i wq[o*4+i] * x[i][j]
    float q[4][4], k[4][4], v[4][4];
    #pragma unroll
    for (int o = 0; o < 4; o++) {
        #pragma unroll
        for (int j = 0; j < 4; j++) {
            float aq = s_b[o], ak = s_b[4 + o], av = s_b[8 + o];
            #pragma unroll
            for (int i = 0; i < 4; i++) {
                const float xi = xv[i][j];
                aq = fmaf(s_w[o * 4 + i],      xi, aq);
                ak = fmaf(s_w[16 + o * 4 + i], xi, ak);
                av = fmaf(s_w[32 + o * 4 + i], xi, av);
            }
            q[o][j] = aq; k[o][j] = ak; v[o][j] = av;
        }
    }

    // ---- Partial scores: ps[c][d] = sum_j q[c][j]*k[d][j]  (this thread's 4 w's)
    float ps[16];
    #pragma unroll
    for (int c = 0; c < 4; c++) {
        #pragma unroll
        for (int d = 0; d < 4; d++) {
            float s = 0.f;
            #pragma unroll
            for (int j = 0; j < 4; j++) s = fmaf(q[c][j], k[d][j], s);
            ps[c * 4 + d] = s;
        }
    }

    // ---- Warp reduce each of the 16 partials, lane 0 writes to smem
    #pragma unroll
    for (int i = 0; i < 16; i++) {
        float s = ps[i];
        #pragma unroll
        for (int off = 16; off > 0; off >>= 1)
            s += __shfl_xor_sync(0xFFFFFFFFu, s, off);
        if (lane == 0) s_red[warp][i] = s;
    }
    __syncthreads();

    // ---- Cross-warp reduce (8 warps) -> scaled scores
    if (tid < 16) {
        float s = 0.f;
        #pragma unroll
        for (int wdx = 0; wdx < 8; wdx++) s += s_red[wdx][tid];
        s_scores[tid] = s * 0.03125f;       // 1/sqrt(1024)
    }
    __syncthreads();

    // ---- Softmax (redundant per thread; 4x4 is trivially cheap)
    float attn[4][4];
    #pragma unroll
    for (int c = 0; c < 4; c++) {
        float m = s_scores[c * 4];
        #pragma unroll
        for (int d = 1; d < 4; d++) m = fmaxf(m, s_scores[c * 4 + d]);
        float sum = 0.f;
        #pragma unroll
        for (int d = 0; d < 4; d++) {
            const float e = __expf(s_scores[c * 4 + d] - m);
            attn[c][d] = e;
            sum += e;
        }
        const float inv = __fdividef(1.0f, sum);
        #pragma unroll
        for (int d = 0; d < 4; d++) attn[c][d] *= inv;
    }

    // ---- out[c][w] = sum_d attn[c][d] * v[d][w]; out is [B,H,C,W]: off = bh*4096 + c*1024 + w
    const int obase = (bh << 12) + w0;
    #pragma unroll
    for (int c = 0; c < 4; c++) {
        float4 r;
        float* rp = &r.x;
        #pragma unroll
        for (int j = 0; j < 4; j++) {
            float s = 0.f;
            #pragma unroll
            for (int d = 0; d < 4; d++) s = fmaf(attn[c][d], v[d][j], s);
            rp[j] = s;
        }
        *reinterpret_cast<float4*>(out + obase + (c << 10)) = r;
    }
}

extern "C" void kernel_launch(void* const* d_in, const int* in_sizes, int n_in,
                              void* d_out, int out_size)
{
    const float* x  = (const float*)d_in[0];
    const float* wq = (const float*)d_in[1];
    const float* bq = (const float*)d_in[2];
    const float* wk = (const float*)d_in[3];
    const float* bk = (const float*)d_in[4];
    const float* wv = (const float*)d_in[5];
    const float* bv = (const float*)d_in[6];
    float* out = (float*)d_out;

    const int B = 16;
    dim3 grid(B * H_DIM);     // 16384 CTAs, one per (b,h)
    dim3 block(THREADS);
    fused_attn_kernel<<<grid, block>>>(x, wq, bq, wk, bk, wv, bv, out);
}

// round 3
// speedup vs baseline: 3.3023x; 3.3023x over previous
#include <cuda_runtime.h>

// B=16, C=4, H=1024, W=1024
// x: [B, C, H, W] fp32 ; out: [B, H, C, W] fp32
// One CTA per (b,h). 256 threads x 4 w each. Fully fused QKV + tiny attention.
// Register-lean restructure: per-pixel q/k are transient, ps accumulated inline.

#define H_DIM 1024
#define W_DIM 1024
#define THREADS 256

__global__ __launch_bounds__(THREADS, 4)
void fused_attn_kernel(const float* __restrict__ x,
                       const float* __restrict__ wq, const float* __restrict__ bq,
                       const float* __restrict__ wk, const float* __restrict__ bk,
                       const float* __restrict__ wv, const float* __restrict__ bv,
                       float* __restrict__ out)
{
    const int bh   = blockIdx.x;            // b*H + h
    const int tid  = threadIdx.x;           // 0..255
    const int lane = tid & 31;
    const int warp = tid >> 5;
    const int w0   = tid << 2;              // 4 w per thread

    __shared__ float s_w[48];               // wq | wk | wv
    __shared__ float s_b[12];               // bq | bk | bv
    __shared__ float s_red[8][16];          // per-warp partial scores
    __shared__ float s_scores[16];          // final 4x4 scaled scores

    if (tid < 16) {
        s_w[tid]      = wq[tid];
        s_w[16 + tid] = wk[tid];
        s_w[32 + tid] = wv[tid];
    }
    if (tid < 4) {
        s_b[tid]     = bq[tid];
        s_b[4 + tid] = bk[tid];
        s_b[8 + tid] = bv[tid];
    }
    __syncthreads();

    // ---- Load x: 4 channels x float4, streaming (read-once)
    const int b = bh >> 10;
    const int h = bh & (H_DIM - 1);
    const int base = ((b << 2) * H_DIM + h) * W_DIM;

    float xv[4][4];
    #pragma unroll
    for (int c = 0; c < 4; c++) {
        const float4 t = __ldcs(reinterpret_cast<const float4*>(
                              x + base + c * (H_DIM * W_DIM) + w0));
        xv[c][0] = t.x; xv[c][1] = t.y; xv[c][2] = t.z; xv[c][3] = t.w;
    }

    // ---- Per-pixel projection with inline score accumulation.
    // Long-lived regs: v[16], ps[16]. q/k live only within one j iteration.
    float v[4][4];          // [channel o][pixel j]
    float ps[16];
    #pragma unroll
    for (int i = 0; i < 16; i++) ps[i] = 0.f;

    #pragma unroll
    for (int j = 0; j < 4; j++) {
        float qj[4], kj[4];
        #pragma unroll
        for (int o = 0; o < 4; o++) {
            float aq = s_b[o], ak = s_b[4 + o], av = s_b[8 + o];
            #pragma unroll
            for (int i = 0; i < 4; i++) {
                const float xi = xv[i][j];
                aq = fmaf(s_w[o * 4 + i],      xi, aq);
                ak = fmaf(s_w[16 + o * 4 + i], xi, ak);
                av = fmaf(s_w[32 + o * 4 + i], xi, av);
            }
            qj[o] = aq; kj[o] = ak; v[o][j] = av;
        }
        #pragma unroll
        for (int c = 0; c < 4; c++)
            #pragma unroll
            for (int d = 0; d < 4; d++)
                ps[c * 4 + d] = fmaf(qj[c], kj[d], ps[c * 4 + d]);
    }

    // ---- Warp butterfly reduce the 16 partials; lane 0 writes
    #pragma unroll
    for (int i = 0; i < 16; i++) {
        float s = ps[i];
        #pragma unroll
        for (int off = 16; off > 0; off >>= 1)
            s += __shfl_xor_sync(0xFFFFFFFFu, s, off);
        if (lane == 0) s_red[warp][i] = s;
    }
    __syncthreads();

    // ---- Cross-warp reduce (8 warps) -> scaled scores
    if (tid < 16) {
        float s = 0.f;
        #pragma unroll
        for (int wdx = 0; wdx < 8; wdx++) s += s_red[wdx][tid];
        s_scores[tid] = s * 0.03125f;       // 1/sqrt(1024)
    }
    __syncthreads();

    // ---- Softmax (redundant per thread; trivial)
    float attn[4][4];
    #pragma unroll
    for (int c = 0; c < 4; c++) {
        float m = s_scores[c * 4];
        #pragma unroll
        for (int d = 1; d < 4; d++) m = fmaxf(m, s_scores[c * 4 + d]);
        float sum = 0.f;
        #pragma unroll
        for (int d = 0; d < 4; d++) {
            const float e = __expf(s_scores[c * 4 + d] - m);
            attn[c][d] = e;
            sum += e;
        }
        const float inv = __fdividef(1.0f, sum);
        #pragma unroll
        for (int d = 0; d < 4; d++) attn[c][d] *= inv;
    }

    // ---- out[c][w] = sum_d attn[c][d] * v[d][w]; streaming stores (write-once)
    const int obase = (bh << 12) + w0;
    #pragma unroll
    for (int c = 0; c < 4; c++) {
        float4 r;
        float* rp = &r.x;
        #pragma unroll
        for (int j = 0; j < 4; j++) {
            float s = 0.f;
            #pragma unroll
            for (int d = 0; d < 4; d++) s = fmaf(attn[c][d], v[d][j], s);
            rp[j] = s;
        }
        __stcs(reinterpret_cast<float4*>(out + obase + (c << 10)), r);
    }
}

extern "C" void kernel_launch(void* const* d_in, const int* in_sizes, int n_in,
                              void* d_out, int out_size)
{
    const float* x  = (const float*)d_in[0];
    const float* wq = (const float*)d_in[1];
    const float* bq = (const float*)d_in[2];
    const float* wk = (const float*)d_in[3];
    const float* bk = (const float*)d_in[4];
    const float* wv = (const float*)d_in[5];
    const float* bv = (const float*)d_in[6];
    float* out = (float*)d_out;

    dim3 grid(16 * H_DIM);    // 16384 CTAs, one per (b,h)
    dim3 block(THREADS);
    fused_attn_kernel<<<grid, block>>>(x, wq, bq, wk, bk, wv, bv, out);
}

// round 4
// speedup vs baseline: 4.9824x; 1.5088x over previous
#include <cuda_runtime.h>

// B=16, C=4, H=1024, W=1024
// x: [B, C, H, W] fp32 ; out: [B, H, C, W] fp32
//
// Moment-based fused kernel. One CTA per (b,h), 256 threads x 4 w.
//   Phase 1: accumulate G = sum_w x x^T (10 sym entries) and m = sum_w x.
//   Reduce 14 values via interleaved butterfly (16 SHFL) + smem cross-warp.
//   Epilogue (warp 0 only): scores from (G,m,weights) -> softmax ->
//   A_eff = attn @ Wv, b_eff = attn @ bv.
//   Phase 2: out = A_eff x + b_eff  (pure 4x4 per pixel).

#define H_DIM 1024
#define W_DIM 1024
#define THREADS 256

__global__ __launch_bounds__(THREADS, 4)
void fused_attn_kernel(const float* __restrict__ x,
                       const float* __restrict__ wq, const float* __restrict__ bq,
                       const float* __restrict__ wk, const float* __restrict__ bk,
                       const float* __restrict__ wv, const float* __restrict__ bv,
                       float* __restrict__ out)
{
    const int bh   = blockIdx.x;
    const int tid  = threadIdx.x;
    const int lane = tid & 31;
    const int warp = tid >> 5;
    const int w0   = tid << 2;

    __shared__ float s_red[8][16];     // per-warp reduced {G[10], m[4], 0, 0}
    __shared__ float s_gm[16];         // CTA-level G,m
    __shared__ float s_sc[16];         // scaled scores
    __shared__ float s_attn[16];       // softmax(scores)
    __shared__ float s_fin[20];        // A_eff[16] | b_eff[4]

    // ---- Load x: 4 channels x float4, streaming
    const int b = bh >> 10;
    const int h = bh & (H_DIM - 1);
    const int base = ((b << 2) * H_DIM + h) * W_DIM;

    float xv[4][4];
    #pragma unroll
    for (int c = 0; c < 4; c++) {
        const float4 t = __ldcs(reinterpret_cast<const float4*>(
                              x + base + c * (H_DIM * W_DIM) + w0));
        xv[c][0] = t.x; xv[c][1] = t.y; xv[c][2] = t.z; xv[c][3] = t.w;
    }

    // ---- Phase 1: second moments. r = {G00,G01,G02,G03,G11,G12,G13,G22,G23,G33, m0..m3, 0,0}
    float r[16];
    #pragma unroll
    for (int i = 0; i < 16; i++) r[i] = 0.f;

    #pragma unroll
    for (int p = 0; p < 4; p++) {
        const float x0 = xv[0][p], x1 = xv[1][p], x2 = xv[2][p], x3 = xv[3][p];
        r[0] = fmaf(x0, x0, r[0]);
        r[1] = fmaf(x0, x1, r[1]);
        r[2] = fmaf(x0, x2, r[2]);
        r[3] = fmaf(x0, x3, r[3]);
        r[4] = fmaf(x1, x1, r[4]);
        r[5] = fmaf(x1, x2, r[5]);
        r[6] = fmaf(x1, x3, r[6]);
        r[7] = fmaf(x2, x2, r[7]);
        r[8] = fmaf(x2, x3, r[8]);
        r[9] = fmaf(x3, x3, r[9]);
        r[10] += x0; r[11] += x1; r[12] += x2; r[13] += x3;
    }

    // ---- Interleaved butterfly: 16 values over 32 lanes in 16 SHFL.
    // After each step, half the slots retire; lane-bit selects which logical
    // element survives. Final: every lane holds full sum of elem (lane>>1)&15.
    #pragma unroll
    for (int i = 0; i < 8; i++) {
        const float a = r[i], bb = r[i + 8];
        const float send = (lane & 16) ? a : bb;
        const float recv = __shfl_xor_sync(0xFFFFFFFFu, send, 16);
        r[i] = ((lane & 16) ? bb : a) + recv;
    }
    #pragma unroll
    for (int i = 0; i < 4; i++) {
        const float a = r[i], bb = r[i + 4];
        const float send = (lane & 8) ? a : bb;
        const float recv = __shfl_xor_sync(0xFFFFFFFFu, send, 8);
        r[i] = ((lane & 8) ? bb : a) + recv;
    }
    #pragma unroll
    for (int i = 0; i < 2; i++) {
        const float a = r[i], bb = r[i + 2];
        const float send = (lane & 4) ? a : bb;
        const float recv = __shfl_xor_sync(0xFFFFFFFFu, send, 4);
        r[i] = ((lane & 4) ? bb : a) + recv;
    }
    {
        const float a = r[0], bb = r[1];
        const float send = (lane & 2) ? a : bb;
        const float recv = __shfl_xor_sync(0xFFFFFFFFu, send, 2);
        r[0] = ((lane & 2) ? bb : a) + recv;
    }
    r[0] += __shfl_xor_sync(0xFFFFFFFFu, r[0], 1);
    if (!(lane & 1)) s_red[warp][(lane >> 1) & 15] = r[0];
    __syncthreads();

    // ---- Epilogue: warp 0 only
    if (warp == 0) {
        if (lane < 16) {
            float s = 0.f;
            #pragma unroll
            for (int wdx = 0; wdx < 8; wdx++) s += s_red[wdx][lane];
            s_gm[lane] = s;
        }
        __syncwarp();

        if (lane < 16) {
            const int c = lane >> 2, d = lane & 3;
            // symmetric index for G
            float m0 = s_gm[10], m1 = s_gm[11], m2 = s_gm[12], m3 = s_gm[13];
            float wqc[4], wkd[4];
            #pragma unroll
            for (int i = 0; i < 4; i++) { wqc[i] = wq[c * 4 + i]; wkd[i] = wk[d * 4 + i]; }
            const float bqc = bq[c], bkd = bk[d];

            // quadratic form wq_c^T G wk_d
            float s = 0.f;
            #pragma unroll
            for (int i = 0; i < 4; i++) {
                float acc = 0.f;
                #pragma unroll
                for (int j = 0; j < 4; j++) {
                    const int lo = i < j ? i : j, hi = i < j ? j : i;
                    const int gi = lo * 4 - (lo * (lo - 1)) / 2 + (hi - lo);
                    acc = fmaf(s_gm[gi], wkd[j], acc);
                }
                s = fmaf(wqc[i], acc, s);
            }
            const float tq = wqc[0]*m0 + wqc[1]*m1 + wqc[2]*m2 + wqc[3]*m3;
            const float tk = wkd[0]*m0 + wkd[1]*m1 + wkd[2]*m2 + wkd[3]*m3;
            s += bqc * tk + bkd * tq + (float)W_DIM * bqc * bkd;
            s_sc[lane] = s * 0.03125f;   // 1/sqrt(1024)
        }
        __syncwarp();

        if (lane < 4) {
            const int c = lane;
            float m = s_sc[c * 4];
            #pragma unroll
            for (int d = 1; d < 4; d++) m = fmaxf(m, s_sc[c * 4 + d]);
            float e[4], sum = 0.f;
            #pragma unroll
            for (int d = 0; d < 4; d++) { e[d] = __expf(s_sc[c * 4 + d] - m); sum += e[d]; }
            const float inv = __fdividef(1.0f, sum);
            #pragma unroll
            for (int d = 0; d < 4; d++) s_attn[c * 4 + d] = e[d] * inv;
        }
        __syncwarp();

        if (lane < 16) {
            const int c = lane >> 2, i = lane & 3;
            float s = 0.f;
            #pragma unroll
            for (int d = 0; d < 4; d++) s = fmaf(s_attn[c * 4 + d], wv[d * 4 + i], s);
            s_fin[lane] = s;            // A_eff[c][i]
        }
        if (lane < 4) {
            float s = 0.f;
            #pragma unroll
            for (int d = 0; d < 4; d++) s = fmaf(s_attn[lane * 4 + d], bv[d], s);
            s_fin[16 + lane] = s;       // b_eff[c]
        }
    }
    __syncthreads();

    // ---- Phase 2: out[c][w] = A_eff[c]·x[:,w] + b_eff[c]
    float ae[4][4], be[4];
    #pragma unroll
    for (int c = 0; c < 4; c++) {
        be[c] = s_fin[16 + c];
        #pragma unroll
        for (int i = 0; i < 4; i++) ae[c][i] = s_fin[c * 4 + i];
    }

    const int obase = (bh << 12) + w0;
    #pragma unroll
    for (int c = 0; c < 4; c++) {
        float4 rr;
        float* rp = &rr.x;
        #pragma unroll
        for (int j = 0; j < 4; j++) {
            float s = be[c];
            #pragma unroll
            for (int i = 0; i < 4; i++) s = fmaf(ae[c][i], xv[i][j], s);
            rp[j] = s;
        }
        __stcs(reinterpret_cast<float4*>(out + obase + (c << 10)), rr);
    }
}

extern "C" void kernel_launch(void* const* d_in, const int* in_sizes, int n_in,
                              void* d_out, int out_size)
{
    const float* x  = (const float*)d_in[0];
    const float* wq = (const float*)d_in[1];
    const float* bq = (const float*)d_in[2];
    const float* wk = (const float*)d_in[3];
    const float* bk = (const float*)d_in[4];
    const float* wv = (const float*)d_in[5];
    const float* bv = (const float*)d_in[6];
    float* out = (float*)d_out;

    dim3 grid(16 * H_DIM);
    dim3 block(THREADS);
    fused_attn_kernel<<<grid, block>>>(x, wq, bq, wk, bk, wv, bv, out);
}